// round 8
// baseline (speedup 1.0000x reference)
#include <cuda_runtime.h>
#include <math.h>

#define THREADS 256
#define RPT 4          // rows per thread (2 packed pairs)
#define KC 32          // codebook size
#define DD 8           // codebook dim

__device__ double g_sum;                 // zero-init at load; reset by last block each run
__device__ unsigned int g_counts[KC];
__device__ unsigned int g_done;

static __device__ __forceinline__ unsigned long long pk2(float lo, float hi) {
    unsigned long long r;
    asm("mov.b64 %0, {%1,%2};" : "=l"(r) : "f"(lo), "f"(hi));
    return r;
}
static __device__ __forceinline__ void upk2(unsigned long long v, float& lo, float& hi) {
    asm("mov.b64 {%0,%1}, %2;" : "=f"(lo), "=f"(hi) : "l"(v));
}
// packed f32x2 fma: d.lo = a.lo*b.lo + c.lo ; d.hi = a.hi*b.hi + c.hi
static __device__ __forceinline__ unsigned long long ffma2(unsigned long long a,
                                                           unsigned long long b,
                                                           unsigned long long c) {
    unsigned long long r;
    asm("fma.rn.f32x2 %0, %1, %2, %3;" : "=l"(r) : "l"(a), "l"(b), "l"(c));
    return r;
}

__global__ __launch_bounds__(THREADS) void vq_fused(
    const float* __restrict__ z, const float* __restrict__ cb,
    float* __restrict__ out, int nrows, long long ndelem, int write_scalars)
{
    __shared__ unsigned long long s_m2c[KC][DD];    // (-2c, -2c) duplicated per element
    __shared__ unsigned long long s_cn[KC];         // (||c||^2, ||c||^2)
    __shared__ float2 s_cpair[KC][5];               // row as 4 float2 pairs, stride 5 -> bank-safe gather
    __shared__ unsigned int s_cnt[KC];
    __shared__ double s_red[THREADS / 32];
    __shared__ int s_islast;

    const int tid = threadIdx.x;
    const int lane = tid & 31;

    if (tid < KC) {
        float v[DD];
        float cn = 0.f;
#pragma unroll
        for (int d = 0; d < DD; d++) {
            v[d] = cb[tid * DD + d];
            cn = fmaf(v[d], v[d], cn);
        }
#pragma unroll
        for (int d = 0; d < DD; d++) {
            float m = -2.f * v[d];
            s_m2c[tid][d] = pk2(m, m);
        }
        s_cn[tid] = pk2(cn, cn);
#pragma unroll
        for (int j = 0; j < 4; j++)
            s_cpair[tid][j] = make_float2(v[2 * j], v[2 * j + 1]);
        s_cnt[tid] = 0u;
    }
    __syncthreads();

    const long long base = (long long)blockIdx.x * (THREADS * RPT) + tid;

    // ---- load 4 rows, pack two rows per 64-bit lane pair; compute ||z||^2 per row ----
    unsigned long long zp[RPT / 2][DD];
    float zn[RPT];
    bool valid[RPT];
#pragma unroll
    for (int p = 0; p < RPT / 2; ++p) {
        long long ra = base + (long long)(2 * p) * THREADS;
        long long rb = ra + THREADS;
        valid[2 * p]     = (ra < nrows);
        valid[2 * p + 1] = (rb < nrows);
        long long la = valid[2 * p] ? ra : 0;
        long long lb = valid[2 * p + 1] ? rb : 0;
        float4 a0 = __ldcs((const float4*)(z + la * DD));
        float4 a1 = __ldcs((const float4*)(z + la * DD + 4));
        float4 b0 = __ldcs((const float4*)(z + lb * DD));
        float4 b1 = __ldcs((const float4*)(z + lb * DD + 4));
        zp[p][0] = pk2(a0.x, b0.x); zp[p][1] = pk2(a0.y, b0.y);
        zp[p][2] = pk2(a0.z, b0.z); zp[p][3] = pk2(a0.w, b0.w);
        zp[p][4] = pk2(a1.x, b1.x); zp[p][5] = pk2(a1.y, b1.y);
        zp[p][6] = pk2(a1.z, b1.z); zp[p][7] = pk2(a1.w, b1.w);
        unsigned long long znp = ffma2(zp[p][0], zp[p][0], 0ULL);
        znp = ffma2(zp[p][1], zp[p][1], znp);
        znp = ffma2(zp[p][2], zp[p][2], znp);
        znp = ffma2(zp[p][3], zp[p][3], znp);
        znp = ffma2(zp[p][4], zp[p][4], znp);
        znp = ffma2(zp[p][5], zp[p][5], znp);
        znp = ffma2(zp[p][6], zp[p][6], znp);
        znp = ffma2(zp[p][7], zp[p][7], znp);
        upk2(znp, zn[2 * p], zn[2 * p + 1]);
    }

    float best[RPT];
    int   bi[RPT];
#pragma unroll
    for (int i = 0; i < RPT; i++) { best[i] = 3.4e38f; bi[i] = 0; }

    // ---- argmin over 32 codes: dist-z2 = ||c||^2 + sum((-2c_d) z_d), 8 ffma2 per pair ----
#pragma unroll 4
    for (int k = 0; k < KC; k++) {
        unsigned long long c0 = s_m2c[k][0], c1 = s_m2c[k][1],
                           c2 = s_m2c[k][2], c3 = s_m2c[k][3],
                           c4 = s_m2c[k][4], c5 = s_m2c[k][5],
                           c6 = s_m2c[k][6], c7 = s_m2c[k][7];
        unsigned long long cnp = s_cn[k];
#pragma unroll
        for (int p = 0; p < RPT / 2; p++) {
            unsigned long long acc = ffma2(zp[p][0], c0, cnp);
            acc = ffma2(zp[p][1], c1, acc);
            acc = ffma2(zp[p][2], c2, acc);
            acc = ffma2(zp[p][3], c3, acc);
            acc = ffma2(zp[p][4], c4, acc);
            acc = ffma2(zp[p][5], c5, acc);
            acc = ffma2(zp[p][6], c6, acc);
            acc = ffma2(zp[p][7], c7, acc);
            float da, db;
            upk2(acc, da, db);
            if (da < best[2 * p])     { best[2 * p] = da;     bi[2 * p] = k; }
            if (db < best[2 * p + 1]) { best[2 * p + 1] = db; bi[2 * p + 1] = k; }
        }
    }

    // ---- epilogue: z_q gather + store, loss = best + ||z||^2, warp-aggregated histogram ----
    float lsum = 0.f;
#pragma unroll
    for (int r = 0; r < RPT; r++) {
        long long row = base + (long long)r * THREADS;
        unsigned int key = valid[r] ? (unsigned int)bi[r] : 0xFFFFFFFFu;
        unsigned int grp = __match_any_sync(0xffffffffu, key);
        bool leader = ((grp & ((1u << lane) - 1u)) == 0u);
        if (valid[r]) {
            lsum += best[r] + zn[r];
            float2 q0 = s_cpair[bi[r]][0];
            float2 q1 = s_cpair[bi[r]][1];
            float2 q2 = s_cpair[bi[r]][2];
            float2 q3 = s_cpair[bi[r]][3];
            __stcs((float4*)(out + row * DD),     make_float4(q0.x, q0.y, q1.x, q1.y));
            __stcs((float4*)(out + row * DD + 4), make_float4(q2.x, q2.y, q3.x, q3.y));
            if (leader) atomicAdd(&s_cnt[bi[r]], (unsigned int)__popc(grp));
        }
    }

    // ---- block reductions -> global accumulators ----
#pragma unroll
    for (int off = 16; off; off >>= 1)
        lsum += __shfl_down_sync(0xffffffffu, lsum, off);
    if ((tid & 31) == 0) s_red[tid >> 5] = (double)lsum;
    __syncthreads();
    if (tid == 0) {
        double t = 0.0;
#pragma unroll
        for (int w = 0; w < THREADS / 32; w++) t += s_red[w];
        atomicAdd(&g_sum, t);
    }
    if (tid < KC) {
        unsigned int c = s_cnt[tid];
        if (c) atomicAdd(&g_counts[tid], c);
    }

    // ---- last-block finalize (threadfence + ticket pattern) ----
    __syncthreads();                 // all atomics above issued
    if (tid == 0) {
        __threadfence();             // make this block's contributions device-visible
        unsigned int ticket = atomicAdd(&g_done, 1u);
        s_islast = (ticket == gridDim.x - 1) ? 1 : 0;
    }
    __syncthreads();

    if (s_islast && tid < 32) {
        unsigned int cnt = g_counts[tid];
        double p = (double)cnt / (double)nrows;
        double term = p * log(p + 1e-10);
#pragma unroll
        for (int off = 16; off; off >>= 1)
            term += __shfl_down_sync(0xffffffffu, term, off);
        if (tid == 0) {
            double s = atomicAdd(&g_sum, 0.0);   // atomic read
            if (write_scalars) {
                out[ndelem]     = (float)((s * 1.25) / (double)ndelem);
                out[ndelem + 1] = (float)exp(-term);
            }
            g_sum = 0.0;                          // reset for next graph replay
        }
        g_counts[tid] = 0u;
        __threadfence();
        if (tid == 0) g_done = 0u;
    }
}

extern "C" void kernel_launch(void* const* d_in, const int* in_sizes, int n_in,
                              void* d_out, int out_size) {
    const float* z  = (const float*)d_in[0];
    const float* cb = (const float*)d_in[1];
    float* out = (float*)d_out;

    int nrows = in_sizes[0] / DD;
    long long ndelem = (long long)nrows * DD;
    int blocks = (nrows + THREADS * RPT - 1) / (THREADS * RPT);
    int write_scalars = ((long long)out_size >= ndelem + 2) ? 1 : 0;

    vq_fused<<<blocks, THREADS>>>(z, cb, out, nrows, ndelem, write_scalars);
}